// round 10
// baseline (speedup 1.0000x reference)
#include <cuda_runtime.h>
#include <cuda_fp16.h>
#include <cstdint>

// ---------------------------------------------------------------------------
// Self-attention, sm_103 baseline ISA. Round 10: fp16 single-product GEMMs
// (numerics frozen since round 7). Lesson of R8 (reg spill) + R9 (1 CTA/SM
// latency exposure): get BOTH the fat 64x64 warp tile (192 B/MMA smem
// traffic -> 67% crossbar ceiling) and 2 CTAs/SM by shrinking the CTA to
// 128 threads (4 warps, 2x2), CTA tile 128x128, 3-stage cp.async.
// ---------------------------------------------------------------------------

#define BMT 128
#define BNT 128
#define BKT 64
#define SSTR 144                   // smem row stride bytes (128B data + 16 pad)
#define TILE_T (128 * SSTR)        // 18432 B per tile (A or B)
#define STAGE_B (2 * TILE_T)       // 36864 B
#define SMEM_SZ (3 * STAGE_B)      // 110592 B (3-stage)

static constexpr long long QKV_ONE = 16384LL * 1024LL;

__device__ __half g_xh[16384LL * 1024];
__device__ __half g_wt[3LL * 1024 * 1024];
__device__ __half g_qkh[2 * 16384LL * 1024];
__device__ __half g_vt[8LL * 1024 * 2048];
__device__ float  g_scores[8LL * 2048 * 2048];
__device__ __half g_ah[8LL * 2048 * 2048];

// ---------------- PTX helpers ----------------
__device__ __forceinline__ uint32_t s2u(const void* p) {
    uint32_t a;
    asm("{ .reg .u64 t; cvta.to.shared.u64 t, %1; cvt.u32.u64 %0, t; }" : "=r"(a) : "l"(p));
    return a;
}
__device__ __forceinline__ void cpasync16(uint32_t d, const void* s) {
    asm volatile("cp.async.cg.shared.global [%0], [%1], 16;" :: "r"(d), "l"(s) : "memory");
}
#define CP_COMMIT() asm volatile("cp.async.commit_group;" ::: "memory")
#define CP_WAIT(n)  asm volatile("cp.async.wait_group %0;" :: "n"(n) : "memory")

__device__ __forceinline__ void ldsm4(uint32_t* r, uint32_t a) {
    asm volatile("ldmatrix.sync.aligned.m8n8.x4.shared.b16 {%0,%1,%2,%3}, [%4];"
                 : "=r"(r[0]), "=r"(r[1]), "=r"(r[2]), "=r"(r[3]) : "r"(a));
}
__device__ __forceinline__ void mma_f16(float* d, const uint32_t* a, const uint32_t* b) {
    asm volatile(
        "mma.sync.aligned.m16n8k16.row.col.f32.f16.f16.f32 "
        "{%0,%1,%2,%3}, {%4,%5,%6,%7}, {%8,%9}, {%0,%1,%2,%3};"
        : "+f"(d[0]), "+f"(d[1]), "+f"(d[2]), "+f"(d[3])
        : "r"(a[0]), "r"(a[1]), "r"(a[2]), "r"(a[3]), "r"(b[0]), "r"(b[1]));
}

// ---------------- fp16 GEMM: C[M,N] = sum_k A[m][k]*B[n][k] ----------------
template <int OUT>   // 0: fp32 C, 1: fp16 C
__global__ __launch_bounds__(128, 2) void h_gemm(
    const __half* __restrict__ Ag, const __half* __restrict__ Bg,
    float* __restrict__ Cf, __half* __restrict__ Ch,
    int K, int lda, int ldb, int ldc,
    long long batA, long long batB, long long batC)
{
    extern __shared__ char smem[];
    const uint32_t sb = s2u(smem);
    const int tid = threadIdx.x;
    const int lane = tid & 31, warp = tid >> 5;
    const int wM = warp & 1;        // 2 warps along M (64 rows each)
    const int wN = warp >> 1;       // 2 warps along N (64 cols each)
    const int lm = lane >> 3, lr = lane & 7;
    const int gid = lane >> 2, tig = lane & 3;

    const long long rowBase = (long long)blockIdx.y * BMT;
    const long long colBase = (long long)blockIdx.x * BNT;
    const char* A = (const char*)(Ag + blockIdx.z * batA);
    const char* B = (const char*)(Bg + blockIdx.z * batB);

    // ldmatrix lane base addresses (add stage offset + ks*32 bytes)
    const uint32_t aBase = (uint32_t)(wM * 64 + (lm & 1) * 8 + lr) * SSTR + ((lm >> 1) * 8) * 2;
    const uint32_t bBase = TILE_T + (uint32_t)(wN * 64 + (lm >> 1) * 8 + lr) * SSTR + ((lm & 1) * 8) * 2;

    float acc[4][8][4];
#pragma unroll
    for (int i = 0; i < 4; i++)
#pragma unroll
        for (int j = 0; j < 8; j++)
#pragma unroll
            for (int c = 0; c < 4; c++) acc[i][j][c] = 0.f;

    const int nCh = K / BKT;

    // loaders: 128 threads, 1 thread = 1 row of 128B = 8 x cp.async 16B
    auto loadA = [&](int c) {
        const uint32_t st = sb + (uint32_t)(c % 3) * STAGE_B;
        const char* g = A + (rowBase + tid) * (long long)lda * 2 + (long long)c * (BKT * 2);
        const uint32_t t0 = st + tid * SSTR;
#pragma unroll
        for (int i = 0; i < 8; i++)
            cpasync16(t0 + i * 16, g + i * 16);
    };
    auto loadB = [&](int c) {
        const uint32_t st = sb + (uint32_t)(c % 3) * STAGE_B + TILE_T;
        const char* g = B + (colBase + tid) * (long long)ldb * 2 + (long long)c * (BKT * 2);
        const uint32_t t0 = st + tid * SSTR;
#pragma unroll
        for (int i = 0; i < 8; i++)
            cpasync16(t0 + i * 16, g + i * 16);
    };

    loadA(0); loadB(0); CP_COMMIT();
    loadA(1); loadB(1); CP_COMMIT();

    for (int c = 0; c < nCh; ++c) {
        if (c + 1 < nCh) { CP_WAIT(1); } else { CP_WAIT(0); }
        __syncthreads();   // stage c visible; all warps past c-1 -> safe to fill (c+2)%3

        const uint32_t stg = sb + (uint32_t)(c % 3) * STAGE_B;
        const bool pf = (c + 2 < nCh);

#pragma unroll
        for (int i = 0; i < 4; i++) {           // ks = i*16
            uint32_t af[4][4], bf[4][4];
            const uint32_t ko = (uint32_t)i * 32;
#pragma unroll
            for (int mt = 0; mt < 4; mt++)
                ldsm4(af[mt], stg + aBase + mt * 16 * SSTR + ko);
#pragma unroll
            for (int p = 0; p < 4; p++)
                ldsm4(bf[p], stg + bBase + p * 16 * SSTR + ko);

            if (i == 0 && pf) loadA(c + 2);     // global prefetch hides under MMAs
            if (i == 1 && pf) { loadB(c + 2); CP_COMMIT(); }

#pragma unroll
            for (int mt = 0; mt < 4; mt++)
#pragma unroll
                for (int nt = 0; nt < 8; nt++)
                    mma_f16(acc[mt][nt], af[mt], &bf[nt >> 1][(nt & 1) * 2]);
        }
    }

    // ---- epilogue ----
#pragma unroll
    for (int mt = 0; mt < 4; mt++) {
        const long long r0 = rowBase + wM * 64 + mt * 16 + gid;
#pragma unroll
        for (int nt = 0; nt < 8; nt++) {
            const long long c0 = colBase + wN * 64 + nt * 8 + tig * 2;
            if (OUT == 1) {
                __half* cp = Ch + blockIdx.z * batC;
                *(__half2*)&cp[r0 * ldc + c0] =
                    __floats2half2_rn(acc[mt][nt][0], acc[mt][nt][1]);
                *(__half2*)&cp[(r0 + 8) * ldc + c0] =
                    __floats2half2_rn(acc[mt][nt][2], acc[mt][nt][3]);
            } else {
                float* cp = Cf + blockIdx.z * batC;
                *(float2*)&cp[r0 * ldc + c0] =
                    make_float2(acc[mt][nt][0], acc[mt][nt][1]);
                *(float2*)&cp[(r0 + 8) * ldc + c0] =
                    make_float2(acc[mt][nt][2], acc[mt][nt][3]);
            }
        }
    }
}

// ---------------- conversion kernels ----------------
__global__ __launch_bounds__(256) void cvt_x(
    const float4* __restrict__ in, __half* __restrict__ out, int n4)
{
    int i = blockIdx.x * 256 + threadIdx.x;
    if (i >= n4) return;
    float4 v = in[i];
    ((__half2*)out)[2 * i]     = __floats2half2_rn(v.x, v.y);
    ((__half2*)out)[2 * i + 1] = __floats2half2_rn(v.z, v.w);
}

// out[z][c][r] = in[z][r][c] as fp16
__global__ __launch_bounds__(256) void transpose_cvt(
    const float* __restrict__ in, __half* __restrict__ out,
    int R, int C, long long batIn, long long batOut)
{
    __shared__ float t[32][33];
    const float* ip = in + blockIdx.z * batIn;
    const long long ob = blockIdx.z * batOut;
    const int c0 = blockIdx.x * 32, r0 = blockIdx.y * 32;
    const int tx = threadIdx.x, ty = threadIdx.y;
#pragma unroll
    for (int i = 0; i < 32; i += 8)
        t[ty + i][tx] = ip[(long long)(r0 + ty + i) * C + c0 + tx];
    __syncthreads();
#pragma unroll
    for (int i = 0; i < 32; i += 8)
        out[ob + (long long)(c0 + ty + i) * R + r0 + tx] = __float2half(t[tx][ty + i]);
}

// softmax over rows of 2048; 1/8 scale folded in; fp16 output
__global__ __launch_bounds__(256) void softmax_h(
    const float* __restrict__ sc, __half* __restrict__ out)
{
    const float SC = 0.125f;
    const long long row = blockIdx.x;
    const float* p = sc + row * 2048;
    const int t = threadIdx.x, lane = t & 31, w = t >> 5;

    float4 v0 = ((const float4*)p)[t];
    float4 v1 = ((const float4*)p)[t + 256];
    float x[8] = {v0.x, v0.y, v0.z, v0.w, v1.x, v1.y, v1.z, v1.w};

    float m = -1e30f;
#pragma unroll
    for (int i = 0; i < 8; i++) { x[i] *= SC; m = fmaxf(m, x[i]); }
#pragma unroll
    for (int o = 16; o > 0; o >>= 1) m = fmaxf(m, __shfl_xor_sync(0xffffffffu, m, o));

    __shared__ float red[8];
    if (lane == 0) red[w] = m;
    __syncthreads();
    float bm = red[0];
#pragma unroll
    for (int i = 1; i < 8; i++) bm = fmaxf(bm, red[i]);

    float s = 0.f;
#pragma unroll
    for (int i = 0; i < 8; i++) { x[i] = expf(x[i] - bm); s += x[i]; }
#pragma unroll
    for (int o = 16; o > 0; o >>= 1) s += __shfl_xor_sync(0xffffffffu, s, o);
    __syncthreads();
    if (lane == 0) red[w] = s;
    __syncthreads();
    float tot = 0.f;
#pragma unroll
    for (int i = 0; i < 8; i++) tot += red[i];
    const float inv = 1.0f / tot;

    __half2* op = (__half2*)(out + row * 2048);
    op[2 * t]       = __floats2half2_rn(x[0] * inv, x[1] * inv);
    op[2 * t + 1]   = __floats2half2_rn(x[2] * inv, x[3] * inv);
    op[2 * t + 512] = __floats2half2_rn(x[4] * inv, x[5] * inv);
    op[2 * t + 513] = __floats2half2_rn(x[6] * inv, x[7] * inv);
}

// ---------------- host ----------------
extern "C" void kernel_launch(void* const* d_in, const int* in_sizes, int n_in,
                              void* d_out, int out_size) {
    const float* x = (const float*)d_in[0];
    const float* w = (const float*)d_in[1];
    float* out = (float*)d_out;

    __half *xh, *wt, *qkh, *vt, *ah;
    float* scores;
    cudaGetSymbolAddress((void**)&xh, g_xh);
    cudaGetSymbolAddress((void**)&wt, g_wt);
    cudaGetSymbolAddress((void**)&qkh, g_qkh);
    cudaGetSymbolAddress((void**)&vt, g_vt);
    cudaGetSymbolAddress((void**)&scores, g_scores);
    cudaGetSymbolAddress((void**)&ah, g_ah);

    cudaFuncSetAttribute(h_gemm<0>, cudaFuncAttributeMaxDynamicSharedMemorySize, SMEM_SZ);
    cudaFuncSetAttribute(h_gemm<1>, cudaFuncAttributeMaxDynamicSharedMemorySize, SMEM_SZ);

    // 1) x -> fp16
    cvt_x<<<16384, 256>>>((const float4*)x, xh, 16384 * 1024 / 4);

    // 2) W transpose -> wt[z][d][h] fp16
    transpose_cvt<<<dim3(32, 32, 3), dim3(32, 8)>>>(
        w, wt, 1024, 1024, 1024LL * 1024, 1024LL * 1024);

    // 3) Q,K projections: [s][d] fp16  (M=16384, N=1024, K=1024; z = Q/K)
    h_gemm<1><<<dim3(8, 128, 2), 128, SMEM_SZ>>>(
        xh, wt, nullptr, qkh,
        1024, 1024, 1024, 1024, 0LL, 1024LL * 1024, QKV_ONE);

    // 4) V projection, produced TRANSPOSED: vt[b][d][s] fp16 (M=1024, N=2048)
    h_gemm<1><<<dim3(16, 8, 8), 128, SMEM_SZ>>>(
        wt + 2LL * 1024 * 1024, xh, nullptr, vt,
        1024, 1024, 1024, 2048, 0LL, 2048LL * 1024, 1024LL * 2048);

    // 5) S = Q @ K^T per batch -> fp32 (M=2048, N=2048, K=1024)
    h_gemm<0><<<dim3(16, 16, 8), 128, SMEM_SZ>>>(
        qkh, qkh + QKV_ONE, scores, nullptr,
        1024, 1024, 1024, 2048, 2048LL * 1024, 2048LL * 1024, 2048LL * 2048);

    // 6) softmax -> fp16 A
    softmax_h<<<16384, 256>>>(scores, ah);

    // 7) out = A @ V per batch (M=2048, N=1024, K=2048); B = vt[d][s] K-major
    h_gemm<0><<<dim3(8, 16, 8), 128, SMEM_SZ>>>(
        ah, vt, out, nullptr,
        2048, 2048, 2048, 1024, 2048LL * 2048, 1024LL * 2048, 2048LL * 1024);
}

// round 11
// speedup vs baseline: 1.2858x; 1.2858x over previous
#include <cuda_runtime.h>
#include <cuda_fp16.h>
#include <cstdint>

// ---------------------------------------------------------------------------
// Self-attention, sm_103 baseline ISA. Round 11: fp16 single-product GEMMs
// (numerics frozen since R7; rel_err must stay 0.0008065866).
// Constraint learned R7-R10: tensor%% tracks warps/SMSP (need 4 => 512
// resident threads => <=128 regs => warp tile 64x32). This round keeps that
// and halves smem traffic instead: one 512-thread CTA (16 warps, 2Mx8N),
// CTA tile 128x256, warp tile 64x32 (176 B/MMA vs 250), 3-stage cp.async
// with wait_group(1) so the single-CTA barrier is skew-only.
// ---------------------------------------------------------------------------

#define BMT 128
#define BNT 256
#define BKT 64
#define SSTR 144                    // smem row stride bytes (128B data + 16 pad)
#define TILE_A (128 * SSTR)         // 18432 B
#define TILE_BB (256 * SSTR)        // 36864 B
#define STAGE_B (TILE_A + TILE_BB)  // 55296 B
#define SMEM_SZ (3 * STAGE_B)       // 165888 B (3-stage, 1 CTA/SM)

static constexpr long long QKV_ONE = 16384LL * 1024LL;

__device__ __half g_xh[16384LL * 1024];
__device__ __half g_wt[3LL * 1024 * 1024];
__device__ __half g_qkh[2 * 16384LL * 1024];
__device__ __half g_vt[8LL * 1024 * 2048];
__device__ float  g_scores[8LL * 2048 * 2048];
__device__ __half g_ah[8LL * 2048 * 2048];

// ---------------- PTX helpers ----------------
__device__ __forceinline__ uint32_t s2u(const void* p) {
    uint32_t a;
    asm("{ .reg .u64 t; cvta.to.shared.u64 t, %1; cvt.u32.u64 %0, t; }" : "=r"(a) : "l"(p));
    return a;
}
__device__ __forceinline__ void cpasync16(uint32_t d, const void* s) {
    asm volatile("cp.async.cg.shared.global [%0], [%1], 16;" :: "r"(d), "l"(s) : "memory");
}
#define CP_COMMIT() asm volatile("cp.async.commit_group;" ::: "memory")
#define CP_WAIT(n)  asm volatile("cp.async.wait_group %0;" :: "n"(n) : "memory")

__device__ __forceinline__ void ldsm4(uint32_t* r, uint32_t a) {
    asm volatile("ldmatrix.sync.aligned.m8n8.x4.shared.b16 {%0,%1,%2,%3}, [%4];"
                 : "=r"(r[0]), "=r"(r[1]), "=r"(r[2]), "=r"(r[3]) : "r"(a));
}
__device__ __forceinline__ void mma_f16(float* d, const uint32_t* a, const uint32_t* b) {
    asm volatile(
        "mma.sync.aligned.m16n8k16.row.col.f32.f16.f16.f32 "
        "{%0,%1,%2,%3}, {%4,%5,%6,%7}, {%8,%9}, {%0,%1,%2,%3};"
        : "+f"(d[0]), "+f"(d[1]), "+f"(d[2]), "+f"(d[3])
        : "r"(a[0]), "r"(a[1]), "r"(a[2]), "r"(a[3]), "r"(b[0]), "r"(b[1]));
}

// ---------------- fp16 GEMM: C[M,N] = sum_k A[m][k]*B[n][k] ----------------
template <int OUT>   // 0: fp32 C, 1: fp16 C
__global__ __launch_bounds__(512, 1) void h_gemm(
    const __half* __restrict__ Ag, const __half* __restrict__ Bg,
    float* __restrict__ Cf, __half* __restrict__ Ch,
    int K, int lda, int ldb, int ldc,
    long long batA, long long batB, long long batC)
{
    extern __shared__ char smem[];
    const uint32_t sb = s2u(smem);
    const int tid = threadIdx.x;
    const int lane = tid & 31, warp = tid >> 5;
    const int wM = warp & 1;        // 2 warps along M (64 rows each)
    const int wN = warp >> 1;       // 8 warps along N (32 cols each)
    const int lm = lane >> 3, lr = lane & 7;
    const int gid = lane >> 2, tig = lane & 3;

    const long long rowBase = (long long)blockIdx.y * BMT;
    const long long colBase = (long long)blockIdx.x * BNT;
    const char* A = (const char*)(Ag + blockIdx.z * batA);
    const char* B = (const char*)(Bg + blockIdx.z * batB);

    // ldmatrix lane base addresses (add stage offset + ks*32 bytes)
    const uint32_t aBase = (uint32_t)(wM * 64 + (lm & 1) * 8 + lr) * SSTR + ((lm >> 1) * 8) * 2;
    const uint32_t bBase = TILE_A + (uint32_t)(wN * 32 + (lm >> 1) * 8 + lr) * SSTR + ((lm & 1) * 8) * 2;

    // cp.async coordinates
    const int ldrA = tid >> 2;           // A row 0..127
    const int cbA  = (tid & 3) * 32;     // 0/32/64/96 within 128B row
    const int ldrB = tid >> 1;           // B row 0..255
    const int cbB  = (tid & 1) * 64;     // 0/64 within 128B row

    float acc[4][4][4];
#pragma unroll
    for (int i = 0; i < 4; i++)
#pragma unroll
        for (int j = 0; j < 4; j++)
#pragma unroll
            for (int c = 0; c < 4; c++) acc[i][j][c] = 0.f;

    const int nCh = K / BKT;

    auto loadA = [&](int c) {
        const uint32_t st = sb + (uint32_t)(c % 3) * STAGE_B;
        const char* g = A + (rowBase + ldrA) * (long long)lda * 2 + (long long)c * (BKT * 2) + cbA;
        const uint32_t t0 = st + ldrA * SSTR + cbA;
        cpasync16(t0, g);
        cpasync16(t0 + 16, g + 16);
    };
    auto loadB = [&](int c) {
        const uint32_t st = sb + (uint32_t)(c % 3) * STAGE_B + TILE_A;
        const char* g = B + (colBase + ldrB) * (long long)ldb * 2 + (long long)c * (BKT * 2) + cbB;
        const uint32_t t0 = st + ldrB * SSTR + cbB;
#pragma unroll
        for (int i = 0; i < 4; i++)
            cpasync16(t0 + i * 16, g + i * 16);
    };

    loadA(0); loadB(0); CP_COMMIT();
    loadA(1); loadB(1); CP_COMMIT();

    for (int c = 0; c < nCh; ++c) {
        if (c + 1 < nCh) { CP_WAIT(1); } else { CP_WAIT(0); }
        __syncthreads();   // stage c visible (landed a chunk ago); safe to refill (c+2)%3

        const uint32_t stg = sb + (uint32_t)(c % 3) * STAGE_B;
        const bool pf = (c + 2 < nCh);

#pragma unroll
        for (int i = 0; i < 4; i++) {           // ks = i*16
            uint32_t af[4][4], bf_[2][4];
            const uint32_t ko = (uint32_t)i * 32;
#pragma unroll
            for (int mt = 0; mt < 4; mt++)
                ldsm4(af[mt], stg + aBase + mt * 16 * SSTR + ko);
#pragma unroll
            for (int p = 0; p < 2; p++)
                ldsm4(bf_[p], stg + bBase + p * 16 * SSTR + ko);

            if (i == 0 && pf) loadA(c + 2);     // prefetch hides under MMAs
            if (i == 1 && pf) { loadB(c + 2); CP_COMMIT(); }

#pragma unroll
            for (int mt = 0; mt < 4; mt++)
#pragma unroll
                for (int nt = 0; nt < 4; nt++)
                    mma_f16(acc[mt][nt], af[mt], &bf_[nt >> 1][(nt & 1) * 2]);
        }
    }

    // ---- epilogue ----
#pragma unroll
    for (int mt = 0; mt < 4; mt++) {
        const long long r0 = rowBase + wM * 64 + mt * 16 + gid;
#pragma unroll
        for (int nt = 0; nt < 4; nt++) {
            const long long c0 = colBase + wN * 32 + nt * 8 + tig * 2;
            if (OUT == 1) {
                __half* cp = Ch + blockIdx.z * batC;
                *(__half2*)&cp[r0 * ldc + c0] =
                    __floats2half2_rn(acc[mt][nt][0], acc[mt][nt][1]);
                *(__half2*)&cp[(r0 + 8) * ldc + c0] =
                    __floats2half2_rn(acc[mt][nt][2], acc[mt][nt][3]);
            } else {
                float* cp = Cf + blockIdx.z * batC;
                *(float2*)&cp[r0 * ldc + c0] =
                    make_float2(acc[mt][nt][0], acc[mt][nt][1]);
                *(float2*)&cp[(r0 + 8) * ldc + c0] =
                    make_float2(acc[mt][nt][2], acc[mt][nt][3]);
            }
        }
    }
}

// ---------------- conversion kernels ----------------
__global__ __launch_bounds__(256) void cvt_x(
    const float4* __restrict__ in, __half* __restrict__ out, int n4)
{
    int i = blockIdx.x * 256 + threadIdx.x;
    if (i >= n4) return;
    float4 v = in[i];
    ((__half2*)out)[2 * i]     = __floats2half2_rn(v.x, v.y);
    ((__half2*)out)[2 * i + 1] = __floats2half2_rn(v.z, v.w);
}

// out[z][c][r] = in[z][r][c] as fp16
__global__ __launch_bounds__(256) void transpose_cvt(
    const float* __restrict__ in, __half* __restrict__ out,
    int R, int C, long long batIn, long long batOut)
{
    __shared__ float t[32][33];
    const float* ip = in + blockIdx.z * batIn;
    const long long ob = blockIdx.z * batOut;
    const int c0 = blockIdx.x * 32, r0 = blockIdx.y * 32;
    const int tx = threadIdx.x, ty = threadIdx.y;
#pragma unroll
    for (int i = 0; i < 32; i += 8)
        t[ty + i][tx] = ip[(long long)(r0 + ty + i) * C + c0 + tx];
    __syncthreads();
#pragma unroll
    for (int i = 0; i < 32; i += 8)
        out[ob + (long long)(c0 + ty + i) * R + r0 + tx] = __float2half(t[tx][ty + i]);
}

// softmax over rows of 2048; 1/8 scale folded in; fp16 output
__global__ __launch_bounds__(256) void softmax_h(
    const float* __restrict__ sc, __half* __restrict__ out)
{
    const float SC = 0.125f;
    const long long row = blockIdx.x;
    const float* p = sc + row * 2048;
    const int t = threadIdx.x, lane = t & 31, w = t >> 5;

    float4 v0 = ((const float4*)p)[t];
    float4 v1 = ((const float4*)p)[t + 256];
    float x[8] = {v0.x, v0.y, v0.z, v0.w, v1.x, v1.y, v1.z, v1.w};

    float m = -1e30f;
#pragma unroll
    for (int i = 0; i < 8; i++) { x[i] *= SC; m = fmaxf(m, x[i]); }
#pragma unroll
    for (int o = 16; o > 0; o >>= 1) m = fmaxf(m, __shfl_xor_sync(0xffffffffu, m, o));

    __shared__ float red[8];
    if (lane == 0) red[w] = m;
    __syncthreads();
    float bm = red[0];
#pragma unroll
    for (int i = 1; i < 8; i++) bm = fmaxf(bm, red[i]);

    float s = 0.f;
#pragma unroll
    for (int i = 0; i < 8; i++) { x[i] = expf(x[i] - bm); s += x[i]; }
#pragma unroll
    for (int o = 16; o > 0; o >>= 1) s += __shfl_xor_sync(0xffffffffu, s, o);
    __syncthreads();
    if (lane == 0) red[w] = s;
    __syncthreads();
    float tot = 0.f;
#pragma unroll
    for (int i = 0; i < 8; i++) tot += red[i];
    const float inv = 1.0f / tot;

    __half2* op = (__half2*)(out + row * 2048);
    op[2 * t]       = __floats2half2_rn(x[0] * inv, x[1] * inv);
    op[2 * t + 1]   = __floats2half2_rn(x[2] * inv, x[3] * inv);
    op[2 * t + 512] = __floats2half2_rn(x[4] * inv, x[5] * inv);
    op[2 * t + 513] = __floats2half2_rn(x[6] * inv, x[7] * inv);
}

// ---------------- host ----------------
extern "C" void kernel_launch(void* const* d_in, const int* in_sizes, int n_in,
                              void* d_out, int out_size) {
    const float* x = (const float*)d_in[0];
    const float* w = (const float*)d_in[1];
    float* out = (float*)d_out;

    __half *xh, *wt, *qkh, *vt, *ah;
    float* scores;
    cudaGetSymbolAddress((void**)&xh, g_xh);
    cudaGetSymbolAddress((void**)&wt, g_wt);
    cudaGetSymbolAddress((void**)&qkh, g_qkh);
    cudaGetSymbolAddress((void**)&vt, g_vt);
    cudaGetSymbolAddress((void**)&scores, g_scores);
    cudaGetSymbolAddress((void**)&ah, g_ah);

    cudaFuncSetAttribute(h_gemm<0>, cudaFuncAttributeMaxDynamicSharedMemorySize, SMEM_SZ);
    cudaFuncSetAttribute(h_gemm<1>, cudaFuncAttributeMaxDynamicSharedMemorySize, SMEM_SZ);

    // 1) x -> fp16
    cvt_x<<<16384, 256>>>((const float4*)x, xh, 16384 * 1024 / 4);

    // 2) W transpose -> wt[z][d][h] fp16
    transpose_cvt<<<dim3(32, 32, 3), dim3(32, 8)>>>(
        w, wt, 1024, 1024, 1024LL * 1024, 1024LL * 1024);

    // 3) Q,K projections: [s][d] fp16  (M=16384, N=1024, K=1024; z = Q/K)
    h_gemm<1><<<dim3(4, 128, 2), 512, SMEM_SZ>>>(
        xh, wt, nullptr, qkh,
        1024, 1024, 1024, 1024, 0LL, 1024LL * 1024, QKV_ONE);

    // 4) V projection, produced TRANSPOSED: vt[b][d][s] fp16 (M=1024, N=2048)
    h_gemm<1><<<dim3(8, 8, 8), 512, SMEM_SZ>>>(
        wt + 2LL * 1024 * 1024, xh, nullptr, vt,
        1024, 1024, 1024, 2048, 0LL, 2048LL * 1024, 1024LL * 2048);

    // 5) S = Q @ K^T per batch -> fp32 (M=2048, N=2048, K=1024)
    h_gemm<0><<<dim3(8, 16, 8), 512, SMEM_SZ>>>(
        qkh, qkh + QKV_ONE, scores, nullptr,
        1024, 1024, 1024, 2048, 2048LL * 1024, 2048LL * 1024, 2048LL * 2048);

    // 6) softmax -> fp16 A
    softmax_h<<<16384, 256>>>(scores, ah);

    // 7) out = A @ V per batch (M=2048, N=1024, K=2048); B = vt[d][s] K-major
    h_gemm<0><<<dim3(4, 16, 8), 512, SMEM_SZ>>>(
        ah, vt, out, nullptr,
        2048, 2048, 2048, 1024, 2048LL * 2048, 1024LL * 2048, 2048LL * 1024);
}